// round 16
// baseline (speedup 1.0000x reference)
#include <cuda_runtime.h>
#include <cuda_fp16.h>
#include <cstdint>
#include <float.h>
#include <mma.h>

using namespace nvcuda;

#define N_NODES 20000
#define N_EDGES 320000
#define ET      340000
#define IN_CH   512
#define HID     128
#define HEADS   4
#define F1      512
#define OUT_CH  30
#define NEG_SLOPE 0.2f

#define M_PAD 20096
#define ZP    32

__device__ __half g_h1h[M_PAD * F1];
__device__ float g_agg1[N_NODES * F1];
__device__ float g_alS1[N_NODES * HEADS];
__device__ float g_alD1[N_NODES * HEADS];
__device__ float g_zpre32[M_PAD * ZP];
__device__ float g_alS2[N_NODES];
__device__ float g_alD2[N_NODES];
__device__ int   g_rowptr[N_NODES + 1];
__device__ int   g_cursor[N_NODES];
__device__ int   g_csr_src[ET];

__device__ __forceinline__ void edge_endpoints(int e, const int* __restrict__ ei,
                                               int& src, int& dst) {
    if (e < N_EDGES) { src = ei[e]; dst = ei[N_EDGES + e]; }
    else { src = e - N_EDGES; dst = src; }
}

__device__ __forceinline__ float lrelu_exp(float v) {
    return __expf(v > 0.f ? v : NEG_SLOPE * v);
}

__device__ __forceinline__ float4 ldhf4(const __half2* p) {
    float2 raw = *(const float2*)p;
    __half2* h = (__half2*)&raw;
    float2 u0 = __half22float2(h[0]);
    float2 u1 = __half22float2(h[1]);
    return make_float4(u0.x, u0.y, u1.x, u1.y);
}

// ================= CSR build =================
__global__ void k_zero_rowptr() {
    int i = blockIdx.x * blockDim.x + threadIdx.x;
    if (i <= N_NODES) g_rowptr[i] = 0;
}
__global__ void k_count(const int* __restrict__ ei) {
    int e = blockIdx.x * blockDim.x + threadIdx.x;
    if (e >= ET) return;
    int src, dst; edge_endpoints(e, ei, src, dst);
    (void)src;
    atomicAdd(&g_rowptr[dst + 1], 1);
}
#define SCAN_CH 20
__global__ __launch_bounds__(1024)
void k_scan() {
    __shared__ int wsum[32];
    int tid = threadIdx.x;
    int lane = tid & 31, warp = tid >> 5;
    int base = tid * SCAN_CH;
    int incl[SCAN_CH];
    int run = 0;
    #pragma unroll
    for (int i = 0; i < SCAN_CH; i++) {
        int idx = base + i;
        int v = (idx <= N_NODES) ? g_rowptr[idx] : 0;
        run += v;
        incl[i] = run;
    }
    int ws = run;
    #pragma unroll
    for (int o = 1; o < 32; o <<= 1) {
        int t = __shfl_up_sync(0xffffffffu, ws, o);
        if (lane >= o) ws += t;
    }
    if (lane == 31) wsum[warp] = ws;
    __syncthreads();
    if (warp == 0) {
        int t = (lane < 32) ? wsum[lane] : 0;
        #pragma unroll
        for (int o = 1; o < 32; o <<= 1) {
            int u = __shfl_up_sync(0xffffffffu, t, o);
            if (lane >= o) t += u;
        }
        wsum[lane] = t;
    }
    __syncthreads();
    int offset = (ws - run) + (warp > 0 ? wsum[warp - 1] : 0);
    #pragma unroll
    for (int i = 0; i < SCAN_CH; i++) {
        int idx = base + i;
        if (idx <= N_NODES) {
            int out = incl[i] + offset;
            g_rowptr[idx] = out;
            if (idx < N_NODES) g_cursor[idx] = out;
        }
    }
}
__global__ void k_scatter(const int* __restrict__ ei) {
    int e = blockIdx.x * blockDim.x + threadIdx.x;
    if (e >= ET) return;
    int src, dst; edge_endpoints(e, ei, src, dst);
    int pos = atomicAdd(&g_cursor[dst], 1);
    g_csr_src[pos] = src;
}

// ========== GEMM1 (tf32): g_h1h = fp16(x @ W1), 128x128 tile, prefetch ==========
#define BM 128
#define BN1 128
#define BK 16
#define LDA (BK + 4)
#define LDB1 (BN1 + 4)
#define LDSC 20
__global__ __launch_bounds__(256, 2)
void k_gemm_tf32(const float* __restrict__ A, const float* __restrict__ B) {
    __shared__ float As[BM][LDA];
    __shared__ float Bs[BK][LDB1];
    __shared__ float sc[8][16][LDSC];
    const int tid = threadIdx.x;
    const int wid = tid >> 5;
    const int lane = tid & 31;
    const int wm = wid >> 1;
    const int wn = wid & 1;
    const int rowBase = blockIdx.y * BM;
    const int colBase = blockIdx.x * BN1;

    wmma::fragment<wmma::accumulator, 16, 16, 8, float> acc[2][4];
    #pragma unroll
    for (int i = 0; i < 2; i++)
        #pragma unroll
        for (int j = 0; j < 4; j++) wmma::fill_fragment(acc[i][j], 0.f);

    float4 pa[2], pb[2];
    #pragma unroll
    for (int t = 0; t < 2; t++) {
        int idx = tid * 2 + t;
        int r = idx >> 2, c = (idx & 3) * 4;
        int gr = rowBase + r;
        pa[t] = (gr < N_NODES) ? *(const float4*)&A[(size_t)gr * IN_CH + c]
                               : make_float4(0.f, 0.f, 0.f, 0.f);
        int br = idx >> 5, bc = (idx & 31) * 4;
        pb[t] = *(const float4*)&B[(size_t)br * F1 + colBase + bc];
    }

    const int T = IN_CH / BK;
    for (int t0 = 0; t0 < T; t0++) {
        #pragma unroll
        for (int t = 0; t < 2; t++) {
            int idx = tid * 2 + t;
            int r = idx >> 2, c = (idx & 3) * 4;
            As[r][c + 0] = wmma::__float_to_tf32(pa[t].x);
            As[r][c + 1] = wmma::__float_to_tf32(pa[t].y);
            As[r][c + 2] = wmma::__float_to_tf32(pa[t].z);
            As[r][c + 3] = wmma::__float_to_tf32(pa[t].w);
            int br = idx >> 5, bc = (idx & 31) * 4;
            Bs[br][bc + 0] = wmma::__float_to_tf32(pb[t].x);
            Bs[br][bc + 1] = wmma::__float_to_tf32(pb[t].y);
            Bs[br][bc + 2] = wmma::__float_to_tf32(pb[t].z);
            Bs[br][bc + 3] = wmma::__float_to_tf32(pb[t].w);
        }
        __syncthreads();
        if (t0 + 1 < T) {
            int k0n = (t0 + 1) * BK;
            #pragma unroll
            for (int t = 0; t < 2; t++) {
                int idx = tid * 2 + t;
                int r = idx >> 2, c = (idx & 3) * 4;
                int gr = rowBase + r;
                pa[t] = (gr < N_NODES) ? *(const float4*)&A[(size_t)gr * IN_CH + k0n + c]
                                       : make_float4(0.f, 0.f, 0.f, 0.f);
                int br = idx >> 5, bc = (idx & 31) * 4;
                pb[t] = *(const float4*)&B[(size_t)(k0n + br) * F1 + colBase + bc];
            }
        }
        #pragma unroll
        for (int kk = 0; kk < BK; kk += 8) {
            wmma::fragment<wmma::matrix_a, 16, 16, 8, wmma::precision::tf32, wmma::row_major> fa[2];
            wmma::fragment<wmma::matrix_b, 16, 16, 8, wmma::precision::tf32, wmma::row_major> fb[4];
            #pragma unroll
            for (int i = 0; i < 2; i++)
                wmma::load_matrix_sync(fa[i], &As[wm * 32 + i * 16][kk], LDA);
            #pragma unroll
            for (int j = 0; j < 4; j++)
                wmma::load_matrix_sync(fb[j], &Bs[kk][wn * 64 + j * 16], LDB1);
            #pragma unroll
            for (int i = 0; i < 2; i++)
                #pragma unroll
                for (int j = 0; j < 4; j++)
                    wmma::mma_sync(acc[i][j], fa[i], fb[j], acc[i][j]);
        }
        __syncthreads();
    }
    #pragma unroll
    for (int i = 0; i < 2; i++)
        #pragma unroll
        for (int j = 0; j < 4; j++) {
            wmma::store_matrix_sync(&sc[wid][0][0], acc[i][j], LDSC, wmma::mem_row_major);
            __syncwarp();
            int r = rowBase + wm * 32 + i * 16 + (lane >> 1);
            int c = colBase + wn * 64 + j * 16 + (lane & 1) * 8;
            const float* srow = &sc[wid][lane >> 1][(lane & 1) * 8];
            __half2 o[4];
            o[0] = __floats2half2_rn(srow[0], srow[1]);
            o[1] = __floats2half2_rn(srow[2], srow[3]);
            o[2] = __floats2half2_rn(srow[4], srow[5]);
            o[3] = __floats2half2_rn(srow[6], srow[7]);
            *(float4*)&g_h1h[(size_t)r * F1 + c] = *(float4*)o;
            __syncwarp();
        }
}

// ====== GEMM2 (tf32) + fused logits2: zpre = agg1 @ W2pad; alS2/alD2 ======
#define BN2 32
#define LDB2 (BN2 + 4)
__global__ __launch_bounds__(256, 2)
void k_gemm2_tf32(const float* __restrict__ W2,
                  const float* __restrict__ aS2, const float* __restrict__ aD2) {
    __shared__ float As[BM][LDA];
    __shared__ float Bs[BK][LDB2];
    const int tid = threadIdx.x;
    const int wid = tid >> 5;
    const int lane = tid & 31;
    const int wm = wid >> 1;
    const int wn = wid & 1;
    const int rowBase = blockIdx.x * BM;

    wmma::fragment<wmma::accumulator, 16, 16, 8, float> acc[2];
    wmma::fill_fragment(acc[0], 0.f);
    wmma::fill_fragment(acc[1], 0.f);

    for (int k0 = 0; k0 < F1; k0 += BK) {
        #pragma unroll
        for (int t = 0; t < 2; t++) {
            int idx = tid * 2 + t;
            int r = idx >> 2;
            int c = (idx & 3) * 4;
            int gr = rowBase + r;
            float4 v = make_float4(0.f, 0.f, 0.f, 0.f);
            if (gr < N_NODES) v = *(const float4*)&g_agg1[(size_t)gr * F1 + k0 + c];
            As[r][c + 0] = wmma::__float_to_tf32(v.x);
            As[r][c + 1] = wmma::__float_to_tf32(v.y);
            As[r][c + 2] = wmma::__float_to_tf32(v.z);
            As[r][c + 3] = wmma::__float_to_tf32(v.w);
        }
        {
            #pragma unroll
            for (int t = 0; t < 2; t++) {
                int idx = tid * 2 + t;
                int r = idx >> 5;
                int c = idx & 31;
                float v = (c < OUT_CH) ? W2[(size_t)(k0 + r) * OUT_CH + c] : 0.f;
                Bs[r][c] = wmma::__float_to_tf32(v);
            }
        }
        __syncthreads();
        #pragma unroll
        for (int kk = 0; kk < BK; kk += 8) {
            wmma::fragment<wmma::matrix_a, 16, 16, 8, wmma::precision::tf32, wmma::row_major> fa[2];
            wmma::fragment<wmma::matrix_b, 16, 16, 8, wmma::precision::tf32, wmma::row_major> fb;
            #pragma unroll
            for (int i = 0; i < 2; i++)
                wmma::load_matrix_sync(fa[i], &As[wm * 32 + i * 16][kk], LDA);
            wmma::load_matrix_sync(fb, &Bs[kk][wn * 16], LDB2);
            #pragma unroll
            for (int i = 0; i < 2; i++)
                wmma::mma_sync(acc[i], fa[i], fb, acc[i]);
        }
        __syncthreads();
    }
    #pragma unroll
    for (int i = 0; i < 2; i++) {
        int r = rowBase + wm * 32 + i * 16;
        int c = wn * 16;
        wmma::store_matrix_sync(&g_zpre32[(size_t)r * ZP + c], acc[i], ZP,
                                wmma::mem_row_major);
    }
    __syncthreads();   // global writes by block now visible block-wide
    // fused logits2: warp wid handles rows [rowBase + wid*16, +16)
    #pragma unroll
    for (int i = 0; i < 16; i++) {
        int r = rowBase + wid * 16 + i;
        float z = (lane < OUT_CH) ? g_zpre32[(size_t)r * ZP + lane] : 0.f;
        float ps = (lane < OUT_CH) ? z * aS2[lane] : 0.f;
        float pd = (lane < OUT_CH) ? z * aD2[lane] : 0.f;
        #pragma unroll
        for (int o = 16; o > 0; o >>= 1) {
            ps += __shfl_down_sync(0xffffffffu, ps, o);
            pd += __shfl_down_sync(0xffffffffu, pd, o);
        }
        if (lane == 0 && r < N_NODES) { g_alS2[r] = ps; g_alD2[r] = pd; }
    }
}

// ================= layer 1 attention logits per node (fp16 h1) =================
__global__ void k_logits1(const float* __restrict__ aS, const float* __restrict__ aD) {
    int n = blockIdx.x;
    int w = threadIdx.x >> 5, lane = threadIdx.x & 31;
    const __half2* hr = (const __half2*)&g_h1h[(size_t)n * F1 + w * HID];
    const float* av = aS + w * HID;
    const float* dv = aD + w * HID;
    float4 h = ldhf4(hr + lane * 2);
    float4 a = *(const float4*)&av[lane * 4];
    float4 d4 = *(const float4*)&dv[lane * 4];
    float s = h.x * a.x + h.y * a.y + h.z * a.z + h.w * a.w;
    float d = h.x * d4.x + h.y * d4.y + h.z * d4.z + h.w * d4.w;
    #pragma unroll
    for (int o = 16; o > 0; o >>= 1) {
        s += __shfl_down_sync(0xffffffffu, s, o);
        d += __shfl_down_sync(0xffffffffu, d, o);
    }
    if (lane == 0) { g_alS1[n * HEADS + w] = s; g_alD1[n * HEADS + w] = d; }
}

// ======= layer 1 aggregate: warp per (node, head-pair), 4-edge unroll, fp16 gather =======
__global__ __launch_bounds__(256)
void k_agg1(const float* __restrict__ b1) {
    int gw = (blockIdx.x * blockDim.x + threadIdx.x) >> 5;
    int lane = threadIdx.x & 31;
    if (gw >= 2 * N_NODES) return;
    int n = gw >> 1;
    int hp = gw & 1;
    int beg = g_rowptr[n], end = g_rowptr[n + 1];
    float2 ad = *(const float2*)&g_alD1[n * 4 + hp * 2];

    float2 den = make_float2(0.f, 0.f);
    for (int e = beg + lane; e < end; e += 32) {
        int src = g_csr_src[e];
        float2 s = *(const float2*)&g_alS1[src * 4 + hp * 2];
        den.x += lrelu_exp(s.x + ad.x);
        den.y += lrelu_exp(s.y + ad.y);
    }
    #pragma unroll
    for (int o = 16; o > 0; o >>= 1) {
        den.x += __shfl_xor_sync(0xffffffffu, den.x, o);
        den.y += __shfl_xor_sync(0xffffffffu, den.y, o);
    }
    float r0 = 1.f / den.x, r1 = 1.f / den.y;

    const size_t colBase = (size_t)(hp * 2) * HID;

    float4 a0 = make_float4(0.f, 0.f, 0.f, 0.f), a1 = a0;
    float4 c0 = a0, c1 = a0;
    int e = beg;
    for (; e + 4 <= end; e += 4) {
        int s0 = g_csr_src[e], s1 = g_csr_src[e + 1];
        int s2 = g_csr_src[e + 2], s3 = g_csr_src[e + 3];
        float2 l0 = *(const float2*)&g_alS1[s0 * 4 + hp * 2];
        float2 l1 = *(const float2*)&g_alS1[s1 * 4 + hp * 2];
        float2 l2 = *(const float2*)&g_alS1[s2 * 4 + hp * 2];
        float2 l3 = *(const float2*)&g_alS1[s3 * 4 + hp * 2];
        const __half2* p0 = (const __half2*)&g_h1h[(size_t)s0 * F1 + colBase];
        const __half2* p1 = (const __half2*)&g_h1h[(size_t)s1 * F1 + colBase];
        const __half2* p2 = (const __half2*)&g_h1h[(size_t)s2 * F1 + colBase];
        const __half2* p3 = (const __half2*)&g_h1h[(size_t)s3 * F1 + colBase];
        float4 h00 = ldhf4(p0 + lane * 2), h01 = ldhf4(p0 + 64 + lane * 2);
        float4 h10 = ldhf4(p1 + lane * 2), h11 = ldhf4(p1 + 64 + lane * 2);
        float4 h20 = ldhf4(p2 + lane * 2), h21 = ldhf4(p2 + 64 + lane * 2);
        float4 h30 = ldhf4(p3 + lane * 2), h31 = ldhf4(p3 + 64 + lane * 2);
        float w00 = lrelu_exp(l0.x + ad.x) * r0, w01 = lrelu_exp(l0.y + ad.y) * r1;
        float w10 = lrelu_exp(l1.x + ad.x) * r0, w11 = lrelu_exp(l1.y + ad.y) * r1;
        float w20 = lrelu_exp(l2.x + ad.x) * r0, w21 = lrelu_exp(l2.y + ad.y) * r1;
        float w30 = lrelu_exp(l3.x + ad.x) * r0, w31 = lrelu_exp(l3.y + ad.y) * r1;
        a0.x = fmaf(w00, h00.x, a0.x); a0.y = fmaf(w00, h00.y, a0.y); a0.z = fmaf(w00, h00.z, a0.z); a0.w = fmaf(w00, h00.w, a0.w);
        a1.x = fmaf(w01, h01.x, a1.x); a1.y = fmaf(w01, h01.y, a1.y); a1.z = fmaf(w01, h01.z, a1.z); a1.w = fmaf(w01, h01.w, a1.w);
        c0.x = fmaf(w10, h10.x, c0.x); c0.y = fmaf(w10, h10.y, c0.y); c0.z = fmaf(w10, h10.z, c0.z); c0.w = fmaf(w10, h10.w, c0.w);
        c1.x = fmaf(w11, h11.x, c1.x); c1.y = fmaf(w11, h11.y, c1.y); c1.z = fmaf(w11, h11.z, c1.z); c1.w = fmaf(w11, h11.w, c1.w);
        a0.x = fmaf(w20, h20.x, a0.x); a0.y = fmaf(w20, h20.y, a0.y); a0.z = fmaf(w20, h20.z, a0.z); a0.w = fmaf(w20, h20.w, a0.w);
        a1.x = fmaf(w21, h21.x, a1.x); a1.y = fmaf(w21, h21.y, a1.y); a1.z = fmaf(w21, h21.z, a1.z); a1.w = fmaf(w21, h21.w, a1.w);
        c0.x = fmaf(w30, h30.x, c0.x); c0.y = fmaf(w30, h30.y, c0.y); c0.z = fmaf(w30, h30.z, c0.z); c0.w = fmaf(w30, h30.w, c0.w);
        c1.x = fmaf(w31, h31.x, c1.x); c1.y = fmaf(w31, h31.y, c1.y); c1.z = fmaf(w31, h31.z, c1.z); c1.w = fmaf(w31, h31.w, c1.w);
    }
    for (; e < end; e++) {
        int src = g_csr_src[e];
        float2 s = *(const float2*)&g_alS1[src * 4 + hp * 2];
        float w0 = lrelu_exp(s.x + ad.x) * r0;
        float w1 = lrelu_exp(s.y + ad.y) * r1;
        const __half2* p = (const __half2*)&g_h1h[(size_t)src * F1 + colBase];
        float4 h0 = ldhf4(p + lane * 2), h1 = ldhf4(p + 64 + lane * 2);
        a0.x = fmaf(w0, h0.x, a0.x); a0.y = fmaf(w0, h0.y, a0.y); a0.z = fmaf(w0, h0.z, a0.z); a0.w = fmaf(w0, h0.w, a0.w);
        a1.x = fmaf(w1, h1.x, a1.x); a1.y = fmaf(w1, h1.y, a1.y); a1.z = fmaf(w1, h1.z, a1.z); a1.w = fmaf(w1, h1.w, a1.w);
    }
    a0.x += c0.x; a0.y += c0.y; a0.z += c0.z; a0.w += c0.w;
    a1.x += c1.x; a1.y += c1.y; a1.z += c1.z; a1.w += c1.w;

    float* outp = &g_agg1[(size_t)n * F1 + colBase];
    float4 acc2[2] = { a0, a1 };
    #pragma unroll
    for (int h = 0; h < 2; h++) {
        float4 bb = *(const float4*)&b1[(hp * 2 + h) * HID + lane * 4];
        float4 v = acc2[h];
        v.x += bb.x; v.y += bb.y; v.z += bb.z; v.w += bb.w;
        v.x = v.x > 0.f ? v.x : expm1f(v.x);
        v.y = v.y > 0.f ? v.y : expm1f(v.y);
        v.z = v.z > 0.f ? v.z : expm1f(v.z);
        v.w = v.w > 0.f ? v.w : expm1f(v.w);
        *(float4*)&outp[h * HID + lane * 4] = v;
    }
}

// ======= layer 2 fused softmax + aggregate + bias -> outZ (2-edge unroll) =======
__global__ __launch_bounds__(256)
void k_agg2(const float* __restrict__ b2, float* __restrict__ outZ) {
    int warp = (blockIdx.x * blockDim.x + threadIdx.x) >> 5;
    int lane = threadIdx.x & 31;
    if (warp >= N_NODES) return;
    int n = warp;
    int beg = g_rowptr[n], end = g_rowptr[n + 1];
    float ad = g_alD2[n];

    float den = 0.f;
    for (int e = beg + lane; e < end; e += 32) {
        int src = g_csr_src[e];
        den += lrelu_exp(g_alS2[src] + ad);
    }
    #pragma unroll
    for (int o = 16; o > 0; o >>= 1) den += __shfl_xor_sync(0xffffffffu, den, o);
    float rden = 1.f / den;

    float accA = 0.f, accB = 0.f;
    int e = beg;
    for (; e + 2 <= end; e += 2) {
        int s0 = g_csr_src[e], s1 = g_csr_src[e + 1];
        float alpha0 = lrelu_exp(g_alS2[s0] + ad) * rden;
        float alpha1 = lrelu_exp(g_alS2[s1] + ad) * rden;
        if (lane < OUT_CH) {
            float z0 = g_zpre32[(size_t)s0 * ZP + lane];
            float z1 = g_zpre32[(size_t)s1 * ZP + lane];
            accA = fmaf(alpha0, z0, accA);
            accB = fmaf(alpha1, z1, accB);
        }
    }
    if (e < end) {
        int src = g_csr_src[e];
        float alpha = lrelu_exp(g_alS2[src] + ad) * rden;
        if (lane < OUT_CH) accA = fmaf(alpha, g_zpre32[(size_t)src * ZP + lane], accA);
    }
    if (lane < OUT_CH) outZ[n * OUT_CH + lane] = accA + accB + b2[lane];
}

// ===== decoder (tf32 wmma): out = z[M,30] @ Wd[30,512] + bd, 128x64 tile =====
#define DBN 64
#define KD  32
#define LDAD (KD + 4)
#define LDBD (DBN + 4)
__global__ __launch_bounds__(256, 2)
void k_decoder_tf32(const float* __restrict__ Wd, const float* __restrict__ bd,
                    float* __restrict__ out, const float* __restrict__ z) {
    __shared__ float As[BM][LDAD];
    __shared__ float Bs[KD][LDBD];
    __shared__ float sc[8][16][LDSC];
    const int tid = threadIdx.x;
    const int wid = tid >> 5;
    const int lane = tid & 31;
    const int wm = wid >> 1;      // 0..3 -> 32 rows
    const int wn = wid & 1;       // 0..1 -> 32 cols
    const int rowBase = blockIdx.y * BM;
    const int colBase = blockIdx.x * DBN;

    // load z tile 128x32 (pad k>=30, rows>=N_NODES with 0)
    for (int idx = tid; idx < BM * KD; idx += 256) {
        int r = idx >> 5;
        int k = idx & 31;
        int gr = rowBase + r;
        float v = 0.f;
        if (k < OUT_CH && gr < N_NODES) v = z[(size_t)gr * OUT_CH + k];
        As[r][k] = wmma::__float_to_tf32(v);
    }
    // load Wd tile 32x64
    for (int idx = tid; idx < KD * DBN; idx += 256) {
        int k = idx >> 6;
        int c = idx & 63;
        float v = (k < OUT_CH) ? Wd[(size_t)k * IN_CH + colBase + c] : 0.f;
        Bs[k][c] = wmma::__float_to_tf32(v);
    }
    __syncthreads();

    wmma::fragment<wmma::accumulator, 16, 16, 8, float> acc[2][2];
    #pragma unroll
    for (int i = 0; i < 2; i++)
        #pragma unroll
        for (int j = 0; j < 2; j++) wmma::fill_fragment(acc[i][j], 0.f);

    #pragma unroll
    for (int kk = 0; kk < KD; kk += 8) {
        wmma::fragment<wmma::matrix_a, 16, 16, 8, wmma::precision::tf32, wmma::row_major> fa[2];
        wmma::fragment<wmma::matrix_b, 16, 16, 8, wmma::precision::tf32, wmma::row_major> fb[2];
        #pragma unroll
        for (int i = 0; i < 2; i++)
            wmma::load_matrix_sync(fa[i], &As[wm * 32 + i * 16][kk], LDAD);
        #pragma unroll
        for (int j = 0; j < 2; j++)
            wmma::load_matrix_sync(fb[j], &Bs[kk][wn * 32 + j * 16], LDBD);
        #pragma unroll
        for (int i = 0; i < 2; i++)
            #pragma unroll
            for (int j = 0; j < 2; j++)
                wmma::mma_sync(acc[i][j], fa[i], fb[j], acc[i][j]);
    }

    // epilogue: stage fragments, add bias, row-guarded stores
    #pragma unroll
    for (int i = 0; i < 2; i++)
        #pragma unroll
        for (int j = 0; j < 2; j++) {
            wmma::store_matrix_sync(&sc[wid][0][0], acc[i][j], LDSC, wmma::mem_row_major);
            __syncwarp();
            int r = rowBase + wm * 32 + i * 16 + (lane >> 1);
            int c = colBase + wn * 32 + j * 16 + (lane & 1) * 8;
            if (r < N_NODES) {
                const float* srow = &sc[wid][lane >> 1][(lane & 1) * 8];
                float4 b0 = *(const float4*)&bd[c];
                float4 b1v = *(const float4*)&bd[c + 4];
                float4 o0 = make_float4(srow[0] + b0.x, srow[1] + b0.y,
                                        srow[2] + b0.z, srow[3] + b0.w);
                float4 o1 = make_float4(srow[4] + b1v.x, srow[5] + b1v.y,
                                        srow[6] + b1v.z, srow[7] + b1v.w);
                *(float4*)&out[(size_t)r * IN_CH + c] = o0;
                *(float4*)&out[(size_t)r * IN_CH + c + 4] = o1;
            }
            __syncwarp();
        }
}

extern "C" void kernel_launch(void* const* d_in, const int* in_sizes, int n_in,
                              void* d_out, int out_size) {
    const float* x   = (const float*)d_in[0];
    const int*   ei  = (const int*)d_in[1];
    const float* W1  = (const float*)d_in[2];
    const float* aS1 = (const float*)d_in[3];
    const float* aD1 = (const float*)d_in[4];
    const float* b1  = (const float*)d_in[5];
    const float* W2  = (const float*)d_in[6];
    const float* aS2 = (const float*)d_in[7];
    const float* aD2 = (const float*)d_in[8];
    const float* b2  = (const float*)d_in[9];
    const float* Wd  = (const float*)d_in[10];
    const float* bd  = (const float*)d_in[11];
    (void)in_sizes; (void)n_in; (void)out_size;

    float* out  = (float*)d_out;
    float* outZ = out + (size_t)N_NODES * IN_CH;

    static cudaStream_t s2 = nullptr;
    static cudaEvent_t evFork = nullptr, evJoin = nullptr;
    if (s2 == nullptr) {
        cudaStreamCreateWithFlags(&s2, cudaStreamNonBlocking);
        cudaEventCreateWithFlags(&evFork, cudaEventDisableTiming);
        cudaEventCreateWithFlags(&evJoin, cudaEventDisableTiming);
    }

    cudaEventRecord(evFork, 0);
    cudaStreamWaitEvent(s2, evFork, 0);
    k_zero_rowptr<<<(N_NODES + 1 + 255) / 256, 256, 0, s2>>>();
    k_count<<<(ET + 255) / 256, 256, 0, s2>>>(ei);
    k_scan<<<1, 1024, 0, s2>>>();
    k_scatter<<<(ET + 255) / 256, 256, 0, s2>>>(ei);
    cudaEventRecord(evJoin, s2);

    {
        dim3 grid(F1 / BN1, M_PAD / BM);
        k_gemm_tf32<<<grid, 256>>>(x, W1);
    }
    k_logits1<<<N_NODES, 128>>>(aS1, aD1);

    cudaStreamWaitEvent(0, evJoin, 0);

    k_agg1<<<(2 * N_NODES * 32 + 255) / 256, 256>>>(b1);

    k_gemm2_tf32<<<M_PAD / BM, 256>>>(W2, aS2, aD2);
    k_agg2<<<(N_NODES * 32 + 255) / 256, 256>>>(b2, outZ);

    {
        dim3 grid(IN_CH / DBN, (N_NODES + BM - 1) / BM);
        k_decoder_tf32<<<grid, 256>>>(Wd, bd, out, outZ);
    }
}

// round 17
// speedup vs baseline: 1.0319x; 1.0319x over previous
#include <cuda_runtime.h>
#include <cuda_fp16.h>
#include <cstdint>
#include <float.h>
#include <mma.h>

using namespace nvcuda;

#define N_NODES 20000
#define N_EDGES 320000
#define ET      340000
#define IN_CH   512
#define HID     128
#define HEADS   4
#define F1      512
#define OUT_CH  30
#define NEG_SLOPE 0.2f

#define M_PAD 20096
#define ZP    32

__device__ __half g_h1h[M_PAD * F1];
__device__ float g_agg1[N_NODES * F1];
__device__ float g_alS1[N_NODES * HEADS];
__device__ float g_alD1[N_NODES * HEADS];
__device__ float g_zpre32[M_PAD * ZP];
__device__ float g_alS2[N_NODES];
__device__ float g_alD2[N_NODES];
__device__ int   g_rowptr[N_NODES + 1];
__device__ int   g_cursor[N_NODES];
__device__ int   g_csr_src[ET];

__device__ __forceinline__ void edge_endpoints(int e, const int* __restrict__ ei,
                                               int& src, int& dst) {
    if (e < N_EDGES) { src = ei[e]; dst = ei[N_EDGES + e]; }
    else { src = e - N_EDGES; dst = src; }
}

__device__ __forceinline__ float lrelu_exp(float v) {
    return __expf(v > 0.f ? v : NEG_SLOPE * v);
}

__device__ __forceinline__ float4 ldhf4(const __half2* p) {
    float2 raw = *(const float2*)p;
    __half2* h = (__half2*)&raw;
    float2 u0 = __half22float2(h[0]);
    float2 u1 = __half22float2(h[1]);
    return make_float4(u0.x, u0.y, u1.x, u1.y);
}

// ================= CSR build =================
__global__ void k_zero_rowptr() {
    int i = blockIdx.x * blockDim.x + threadIdx.x;
    if (i <= N_NODES) g_rowptr[i] = 0;
}
__global__ void k_count(const int* __restrict__ ei) {
    int e = blockIdx.x * blockDim.x + threadIdx.x;
    if (e >= ET) return;
    int src, dst; edge_endpoints(e, ei, src, dst);
    (void)src;
    atomicAdd(&g_rowptr[dst + 1], 1);
}
#define SCAN_CH 20
__global__ __launch_bounds__(1024)
void k_scan() {
    __shared__ int wsum[32];
    int tid = threadIdx.x;
    int lane = tid & 31, warp = tid >> 5;
    int base = tid * SCAN_CH;
    int incl[SCAN_CH];
    int run = 0;
    #pragma unroll
    for (int i = 0; i < SCAN_CH; i++) {
        int idx = base + i;
        int v = (idx <= N_NODES) ? g_rowptr[idx] : 0;
        run += v;
        incl[i] = run;
    }
    int ws = run;
    #pragma unroll
    for (int o = 1; o < 32; o <<= 1) {
        int t = __shfl_up_sync(0xffffffffu, ws, o);
        if (lane >= o) ws += t;
    }
    if (lane == 31) wsum[warp] = ws;
    __syncthreads();
    if (warp == 0) {
        int t = (lane < 32) ? wsum[lane] : 0;
        #pragma unroll
        for (int o = 1; o < 32; o <<= 1) {
            int u = __shfl_up_sync(0xffffffffu, t, o);
            if (lane >= o) t += u;
        }
        wsum[lane] = t;
    }
    __syncthreads();
    int offset = (ws - run) + (warp > 0 ? wsum[warp - 1] : 0);
    #pragma unroll
    for (int i = 0; i < SCAN_CH; i++) {
        int idx = base + i;
        if (idx <= N_NODES) {
            int out = incl[i] + offset;
            g_rowptr[idx] = out;
            if (idx < N_NODES) g_cursor[idx] = out;
        }
    }
}
__global__ void k_scatter(const int* __restrict__ ei) {
    int e = blockIdx.x * blockDim.x + threadIdx.x;
    if (e >= ET) return;
    int src, dst; edge_endpoints(e, ei, src, dst);
    int pos = atomicAdd(&g_cursor[dst], 1);
    g_csr_src[pos] = src;
}

// ===== GEMM1 (tf32): g_h1h = fp16(x @ W1), 128x128 tile, prefetch, fused logits1 =====
// BN1 == HID: each block covers exactly one attention head -> logits close in-block.
#define BM 128
#define BN1 128
#define BK 16
#define LDA (BK + 4)
#define LDB1 (BN1 + 4)
#define LDSC 20
__global__ __launch_bounds__(256, 2)
void k_gemm_tf32(const float* __restrict__ A, const float* __restrict__ B,
                 const float* __restrict__ aS1, const float* __restrict__ aD1) {
    __shared__ float As[BM][LDA];
    __shared__ float Bs[BK][LDB1];
    __shared__ float sc[8][16][LDSC];
    __shared__ float slS[BM], slD[BM];
    const int tid = threadIdx.x;
    const int wid = tid >> 5;
    const int lane = tid & 31;
    const int wm = wid >> 1;
    const int wn = wid & 1;
    const int rowBase = blockIdx.y * BM;
    const int colBase = blockIdx.x * BN1;       // == head * HID
    const int head = blockIdx.x;

    if (tid < BM) { slS[tid] = 0.f; slD[tid] = 0.f; }

    wmma::fragment<wmma::accumulator, 16, 16, 8, float> acc[2][4];
    #pragma unroll
    for (int i = 0; i < 2; i++)
        #pragma unroll
        for (int j = 0; j < 4; j++) wmma::fill_fragment(acc[i][j], 0.f);

    float4 pa[2], pb[2];
    #pragma unroll
    for (int t = 0; t < 2; t++) {
        int idx = tid * 2 + t;
        int r = idx >> 2, c = (idx & 3) * 4;
        int gr = rowBase + r;
        pa[t] = (gr < N_NODES) ? *(const float4*)&A[(size_t)gr * IN_CH + c]
                               : make_float4(0.f, 0.f, 0.f, 0.f);
        int br = idx >> 5, bc = (idx & 31) * 4;
        pb[t] = *(const float4*)&B[(size_t)br * F1 + colBase + bc];
    }

    const int T = IN_CH / BK;
    for (int t0 = 0; t0 < T; t0++) {
        #pragma unroll
        for (int t = 0; t < 2; t++) {
            int idx = tid * 2 + t;
            int r = idx >> 2, c = (idx & 3) * 4;
            As[r][c + 0] = wmma::__float_to_tf32(pa[t].x);
            As[r][c + 1] = wmma::__float_to_tf32(pa[t].y);
            As[r][c + 2] = wmma::__float_to_tf32(pa[t].z);
            As[r][c + 3] = wmma::__float_to_tf32(pa[t].w);
            int br = idx >> 5, bc = (idx & 31) * 4;
            Bs[br][bc + 0] = wmma::__float_to_tf32(pb[t].x);
            Bs[br][bc + 1] = wmma::__float_to_tf32(pb[t].y);
            Bs[br][bc + 2] = wmma::__float_to_tf32(pb[t].z);
            Bs[br][bc + 3] = wmma::__float_to_tf32(pb[t].w);
        }
        __syncthreads();
        if (t0 + 1 < T) {
            int k0n = (t0 + 1) * BK;
            #pragma unroll
            for (int t = 0; t < 2; t++) {
                int idx = tid * 2 + t;
                int r = idx >> 2, c = (idx & 3) * 4;
                int gr = rowBase + r;
                pa[t] = (gr < N_NODES) ? *(const float4*)&A[(size_t)gr * IN_CH + k0n + c]
                                       : make_float4(0.f, 0.f, 0.f, 0.f);
                int br = idx >> 5, bc = (idx & 31) * 4;
                pb[t] = *(const float4*)&B[(size_t)(k0n + br) * F1 + colBase + bc];
            }
        }
        #pragma unroll
        for (int kk = 0; kk < BK; kk += 8) {
            wmma::fragment<wmma::matrix_a, 16, 16, 8, wmma::precision::tf32, wmma::row_major> fa[2];
            wmma::fragment<wmma::matrix_b, 16, 16, 8, wmma::precision::tf32, wmma::row_major> fb[4];
            #pragma unroll
            for (int i = 0; i < 2; i++)
                wmma::load_matrix_sync(fa[i], &As[wm * 32 + i * 16][kk], LDA);
            #pragma unroll
            for (int j = 0; j < 4; j++)
                wmma::load_matrix_sync(fb[j], &Bs[kk][wn * 64 + j * 16], LDB1);
            #pragma unroll
            for (int i = 0; i < 2; i++)
                #pragma unroll
                for (int j = 0; j < 4; j++)
                    wmma::mma_sync(acc[i][j], fa[i], fb[j], acc[i][j]);
        }
        __syncthreads();
    }

    // epilogue: stage, fp16 store, and accumulate logits partials
    float ps[2] = {0.f, 0.f}, pd[2] = {0.f, 0.f};
    #pragma unroll
    for (int i = 0; i < 2; i++)
        #pragma unroll
        for (int j = 0; j < 4; j++) {
            wmma::store_matrix_sync(&sc[wid][0][0], acc[i][j], LDSC, wmma::mem_row_major);
            __syncwarp();
            int r = rowBase + wm * 32 + i * 16 + (lane >> 1);
            int c = colBase + wn * 64 + j * 16 + (lane & 1) * 8;
            const float* srow = &sc[wid][lane >> 1][(lane & 1) * 8];
            __half2 o[4];
            o[0] = __floats2half2_rn(srow[0], srow[1]);
            o[1] = __floats2half2_rn(srow[2], srow[3]);
            o[2] = __floats2half2_rn(srow[4], srow[5]);
            o[3] = __floats2half2_rn(srow[6], srow[7]);
            *(float4*)&g_h1h[(size_t)r * F1 + c] = *(float4*)o;
            #pragma unroll
            for (int t = 0; t < 8; t++) {
                // use the rounded fp16 value so logits match what agg1 gathers
                float hv = (t < 4) ? ((t < 2) ? ((t == 0) ? __low2float(o[0]) : __high2float(o[0]))
                                              : ((t == 2) ? __low2float(o[1]) : __high2float(o[1])))
                                   : ((t < 6) ? ((t == 4) ? __low2float(o[2]) : __high2float(o[2]))
                                              : ((t == 6) ? __low2float(o[3]) : __high2float(o[3])));
                ps[i] = fmaf(hv, aS1[c + t], ps[i]);
                pd[i] = fmaf(hv, aD1[c + t], pd[i]);
            }
            __syncwarp();
        }
    // pair-reduce (lanes 2k,2k+1 share a row), then smem-atomic across the 2 col-warps
    #pragma unroll
    for (int i = 0; i < 2; i++) {
        ps[i] += __shfl_down_sync(0xffffffffu, ps[i], 1);
        pd[i] += __shfl_down_sync(0xffffffffu, pd[i], 1);
        if ((lane & 1) == 0) {
            int rloc = wm * 32 + i * 16 + (lane >> 1);
            atomicAdd(&slS[rloc], ps[i]);
            atomicAdd(&slD[rloc], pd[i]);
        }
    }
    __syncthreads();
    if (tid < BM) {
        int n = rowBase + tid;
        if (n < N_NODES) {
            g_alS1[n * HEADS + head] = slS[tid];
            g_alD1[n * HEADS + head] = slD[tid];
        }
    }
}

// ========== GEMM2 (tf32): g_zpre32 = agg1 @ W2pad ==========
#define BN2 32
#define LDB2 (BN2 + 4)
__global__ __launch_bounds__(256, 2)
void k_gemm2_tf32(const float* __restrict__ W2) {
    __shared__ float As[BM][LDA];
    __shared__ float Bs[BK][LDB2];
    const int tid = threadIdx.x;
    const int wid = tid >> 5;
    const int wm = wid >> 1;
    const int wn = wid & 1;
    const int rowBase = blockIdx.x * BM;

    wmma::fragment<wmma::accumulator, 16, 16, 8, float> acc[2];
    wmma::fill_fragment(acc[0], 0.f);
    wmma::fill_fragment(acc[1], 0.f);

    for (int k0 = 0; k0 < F1; k0 += BK) {
        #pragma unroll
        for (int t = 0; t < 2; t++) {
            int idx = tid * 2 + t;
            int r = idx >> 2;
            int c = (idx & 3) * 4;
            int gr = rowBase + r;
            float4 v = make_float4(0.f, 0.f, 0.f, 0.f);
            if (gr < N_NODES) v = *(const float4*)&g_agg1[(size_t)gr * F1 + k0 + c];
            As[r][c + 0] = wmma::__float_to_tf32(v.x);
            As[r][c + 1] = wmma::__float_to_tf32(v.y);
            As[r][c + 2] = wmma::__float_to_tf32(v.z);
            As[r][c + 3] = wmma::__float_to_tf32(v.w);
        }
        {
            #pragma unroll
            for (int t = 0; t < 2; t++) {
                int idx = tid * 2 + t;
                int r = idx >> 5;
                int c = idx & 31;
                float v = (c < OUT_CH) ? W2[(size_t)(k0 + r) * OUT_CH + c] : 0.f;
                Bs[r][c] = wmma::__float_to_tf32(v);
            }
        }
        __syncthreads();
        #pragma unroll
        for (int kk = 0; kk < BK; kk += 8) {
            wmma::fragment<wmma::matrix_a, 16, 16, 8, wmma::precision::tf32, wmma::row_major> fa[2];
            wmma::fragment<wmma::matrix_b, 16, 16, 8, wmma::precision::tf32, wmma::row_major> fb;
            #pragma unroll
            for (int i = 0; i < 2; i++)
                wmma::load_matrix_sync(fa[i], &As[wm * 32 + i * 16][kk], LDA);
            wmma::load_matrix_sync(fb, &Bs[kk][wn * 16], LDB2);
            #pragma unroll
            for (int i = 0; i < 2; i++)
                wmma::mma_sync(acc[i], fa[i], fb, acc[i]);
        }
        __syncthreads();
    }
    #pragma unroll
    for (int i = 0; i < 2; i++) {
        int r = rowBase + wm * 32 + i * 16;
        int c = wn * 16;
        wmma::store_matrix_sync(&g_zpre32[(size_t)r * ZP + c], acc[i], ZP,
                                wmma::mem_row_major);
    }
}

// ================= logits2: warp per node =================
__global__ __launch_bounds__(256)
void k_logits2(const float* __restrict__ aS2, const float* __restrict__ aD2) {
    int warp = (blockIdx.x * blockDim.x + threadIdx.x) >> 5;
    int lane = threadIdx.x & 31;
    if (warp >= N_NODES) return;
    float z = (lane < OUT_CH) ? g_zpre32[(size_t)warp * ZP + lane] : 0.f;
    float ps = (lane < OUT_CH) ? z * aS2[lane] : 0.f;
    float pd = (lane < OUT_CH) ? z * aD2[lane] : 0.f;
    #pragma unroll
    for (int o = 16; o > 0; o >>= 1) {
        ps += __shfl_down_sync(0xffffffffu, ps, o);
        pd += __shfl_down_sync(0xffffffffu, pd, o);
    }
    if (lane == 0) { g_alS2[warp] = ps; g_alD2[warp] = pd; }
}

// ======= layer 1 aggregate: warp per (node, head-pair), 4-edge unroll, fp16 gather =======
__global__ __launch_bounds__(256)
void k_agg1(const float* __restrict__ b1) {
    int gw = (blockIdx.x * blockDim.x + threadIdx.x) >> 5;
    int lane = threadIdx.x & 31;
    if (gw >= 2 * N_NODES) return;
    int n = gw >> 1;
    int hp = gw & 1;
    int beg = g_rowptr[n], end = g_rowptr[n + 1];
    float2 ad = *(const float2*)&g_alD1[n * 4 + hp * 2];

    float2 den = make_float2(0.f, 0.f);
    for (int e = beg + lane; e < end; e += 32) {
        int src = g_csr_src[e];
        float2 s = *(const float2*)&g_alS1[src * 4 + hp * 2];
        den.x += lrelu_exp(s.x + ad.x);
        den.y += lrelu_exp(s.y + ad.y);
    }
    #pragma unroll
    for (int o = 16; o > 0; o >>= 1) {
        den.x += __shfl_xor_sync(0xffffffffu, den.x, o);
        den.y += __shfl_xor_sync(0xffffffffu, den.y, o);
    }
    float r0 = 1.f / den.x, r1 = 1.f / den.y;

    const size_t colBase = (size_t)(hp * 2) * HID;

    float4 a0 = make_float4(0.f, 0.f, 0.f, 0.f), a1 = a0;
    float4 c0 = a0, c1 = a0;
    int e = beg;
    for (; e + 4 <= end; e += 4) {
        int s0 = g_csr_src[e], s1 = g_csr_src[e + 1];
        int s2 = g_csr_src[e + 2], s3 = g_csr_src[e + 3];
        float2 l0 = *(const float2*)&g_alS1[s0 * 4 + hp * 2];
        float2 l1 = *(const float2*)&g_alS1[s1 * 4 + hp * 2];
        float2 l2 = *(const float2*)&g_alS1[s2 * 4 + hp * 2];
        float2 l3 = *(const float2*)&g_alS1[s3 * 4 + hp * 2];
        const __half2* p0 = (const __half2*)&g_h1h[(size_t)s0 * F1 + colBase];
        const __half2* p1 = (const __half2*)&g_h1h[(size_t)s1 * F1 + colBase];
        const __half2* p2 = (const __half2*)&g_h1h[(size_t)s2 * F1 + colBase];
        const __half2* p3 = (const __half2*)&g_h1h[(size_t)s3 * F1 + colBase];
        float4 h00 = ldhf4(p0 + lane * 2), h01 = ldhf4(p0 + 64 + lane * 2);
        float4 h10 = ldhf4(p1 + lane * 2), h11 = ldhf4(p1 + 64 + lane * 2);
        float4 h20 = ldhf4(p2 + lane * 2), h21 = ldhf4(p2 + 64 + lane * 2);
        float4 h30 = ldhf4(p3 + lane * 2), h31 = ldhf4(p3 + 64 + lane * 2);
        float w00 = lrelu_exp(l0.x + ad.x) * r0, w01 = lrelu_exp(l0.y + ad.y) * r1;
        float w10 = lrelu_exp(l1.x + ad.x) * r0, w11 = lrelu_exp(l1.y + ad.y) * r1;
        float w20 = lrelu_exp(l2.x + ad.x) * r0, w21 = lrelu_exp(l2.y + ad.y) * r1;
        float w30 = lrelu_exp(l3.x + ad.x) * r0, w31 = lrelu_exp(l3.y + ad.y) * r1;
        a0.x = fmaf(w00, h00.x, a0.x); a0.y = fmaf(w00, h00.y, a0.y); a0.z = fmaf(w00, h00.z, a0.z); a0.w = fmaf(w00, h00.w, a0.w);
        a1.x = fmaf(w01, h01.x, a1.x); a1.y = fmaf(w01, h01.y, a1.y); a1.z = fmaf(w01, h01.z, a1.z); a1.w = fmaf(w01, h01.w, a1.w);
        c0.x = fmaf(w10, h10.x, c0.x); c0.y = fmaf(w10, h10.y, c0.y); c0.z = fmaf(w10, h10.z, c0.z); c0.w = fmaf(w10, h10.w, c0.w);
        c1.x = fmaf(w11, h11.x, c1.x); c1.y = fmaf(w11, h11.y, c1.y); c1.z = fmaf(w11, h11.z, c1.z); c1.w = fmaf(w11, h11.w, c1.w);
        a0.x = fmaf(w20, h20.x, a0.x); a0.y = fmaf(w20, h20.y, a0.y); a0.z = fmaf(w20, h20.z, a0.z); a0.w = fmaf(w20, h20.w, a0.w);
        a1.x = fmaf(w21, h21.x, a1.x); a1.y = fmaf(w21, h21.y, a1.y); a1.z = fmaf(w21, h21.z, a1.z); a1.w = fmaf(w21, h21.w, a1.w);
        c0.x = fmaf(w30, h30.x, c0.x); c0.y = fmaf(w30, h30.y, c0.y); c0.z = fmaf(w30, h30.z, c0.z); c0.w = fmaf(w30, h30.w, c0.w);
        c1.x = fmaf(w31, h31.x, c1.x); c1.y = fmaf(w31, h31.y, c1.y); c1.z = fmaf(w31, h31.z, c1.z); c1.w = fmaf(w31, h31.w, c1.w);
    }
    for (; e < end; e++) {
        int src = g_csr_src[e];
        float2 s = *(const float2*)&g_alS1[src * 4 + hp * 2];
        float w0 = lrelu_exp(s.x + ad.x) * r0;
        float w1 = lrelu_exp(s.y + ad.y) * r1;
        const __half2* p = (const __half2*)&g_h1h[(size_t)src * F1 + colBase];
        float4 h0 = ldhf4(p + lane * 2), h1 = ldhf4(p + 64 + lane * 2);
        a0.x = fmaf(w0, h0.x, a0.x); a0.y = fmaf(w0, h0.y, a0.y); a0.z = fmaf(w0, h0.z, a0.z); a0.w = fmaf(w0, h0.w, a0.w);
        a1.x = fmaf(w1, h1.x, a1.x); a1.y = fmaf(w1, h1.y, a1.y); a1.z = fmaf(w1, h1.z, a1.z); a1.w = fmaf(w1, h1.w, a1.w);
    }
    a0.x += c0.x; a0.y += c0.y; a0.z += c0.z; a0.w += c0.w;
    a1.x += c1.x; a1.y += c1.y; a1.z += c1.z; a1.w += c1.w;

    float* outp = &g_agg1[(size_t)n * F1 + colBase];
    float4 acc2[2] = { a0, a1 };
    #pragma unroll
    for (int h = 0; h < 2; h++) {
        float4 bb = *(const float4*)&b1[(hp * 2 + h) * HID + lane * 4];
        float4 v = acc2[h];
        v.x += bb.x; v.y += bb.y; v.z += bb.z; v.w += bb.w;
        v.x = v.x > 0.f ? v.x : expm1f(v.x);
        v.y = v.y > 0.f ? v.y : expm1f(v.y);
        v.z = v.z > 0.f ? v.z : expm1f(v.z);
        v.w = v.w > 0.f ? v.w : expm1f(v.w);
        *(float4*)&outp[h * HID + lane * 4] = v;
    }
}

// ======= layer 2 fused softmax + aggregate + bias -> outZ (4-edge unroll) =======
__global__ __launch_bounds__(256)
void k_agg2(const float* __restrict__ b2, float* __restrict__ outZ) {
    int warp = (blockIdx.x * blockDim.x + threadIdx.x) >> 5;
    int lane = threadIdx.x & 31;
    if (warp >= N_NODES) return;
    int n = warp;
    int beg = g_rowptr[n], end = g_rowptr[n + 1];
    float ad = g_alD2[n];

    float den = 0.f;
    for (int e = beg + lane; e < end; e += 32) {
        int src = g_csr_src[e];
        den += lrelu_exp(g_alS2[src] + ad);
    }
    #pragma unroll
    for (int o = 16; o > 0; o >>= 1) den += __shfl_xor_sync(0xffffffffu, den, o);
    float rden = 1.f / den;

    float accA = 0.f, accB = 0.f, accC = 0.f, accD = 0.f;
    int e = beg;
    for (; e + 4 <= end; e += 4) {
        int s0 = g_csr_src[e], s1 = g_csr_src[e + 1];
        int s2 = g_csr_src[e + 2], s3 = g_csr_src[e + 3];
        float al0 = lrelu_exp(g_alS2[s0] + ad) * rden;
        float al1 = lrelu_exp(g_alS2[s1] + ad) * rden;
        float al2 = lrelu_exp(g_alS2[s2] + ad) * rden;
        float al3 = lrelu_exp(g_alS2[s3] + ad) * rden;
        if (lane < OUT_CH) {
            float z0 = g_zpre32[(size_t)s0 * ZP + lane];
            float z1 = g_zpre32[(size_t)s1 * ZP + lane];
            float z2 = g_zpre32[(size_t)s2 * ZP + lane];
            float z3 = g_zpre32[(size_t)s3 * ZP + lane];
            accA = fmaf(al0, z0, accA);
            accB = fmaf(al1, z1, accB);
            accC = fmaf(al2, z2, accC);
            accD = fmaf(al3, z3, accD);
        }
    }
    for (; e < end; e++) {
        int src = g_csr_src[e];
        float alpha = lrelu_exp(g_alS2[src] + ad) * rden;
        if (lane < OUT_CH) accA = fmaf(alpha, g_zpre32[(size_t)src * ZP + lane], accA);
    }
    if (lane < OUT_CH)
        outZ[n * OUT_CH + lane] = (accA + accB) + (accC + accD) + b2[lane];
}

// ================= decoder tiled (R15 version) =================
#define DBN 64
__global__ __launch_bounds__(256, 2)
void k_decodert(const float* __restrict__ Wd, const float* __restrict__ bd,
                float* __restrict__ out, const float* __restrict__ z) {
    __shared__ float As[32][BM + 4];
    __shared__ float Bs[32][DBN];
    const int tid = threadIdx.x;
    const int tr = tid >> 4;
    const int tc = tid & 15;
    const int rowBase = blockIdx.y * BM;
    const int colBase = blockIdx.x * DBN;

    for (int idx = tid; idx < BM * 32; idx += 256) {
        int r = idx >> 5;
        int k = idx & 31;
        int gr = rowBase + r;
        float v = 0.f;
        if (k < OUT_CH && gr < N_NODES) v = z[(size_t)gr * OUT_CH + k];
        As[k][r] = v;
    }
    for (int idx = tid; idx < 32 * DBN; idx += 256) {
        int k = idx >> 6;
        int c = idx & 63;
        Bs[k][c] = (k < OUT_CH) ? Wd[(size_t)k * IN_CH + colBase + c] : 0.f;
    }
    __syncthreads();

    float acc[8][4];
    {
        float4 bb = *(const float4*)&bd[colBase + tc * 4];
        #pragma unroll
        for (int i = 0; i < 8; i++) {
            acc[i][0] = bb.x; acc[i][1] = bb.y; acc[i][2] = bb.z; acc[i][3] = bb.w;
        }
    }
    #pragma unroll
    for (int k = 0; k < OUT_CH; k++) {
        float a[8], b[4];
        #pragma unroll
        for (int i = 0; i < 8; i += 4)
            *(float4*)&a[i] = *(const float4*)&As[k][tr * 8 + i];
        *(float4*)&b[0] = *(const float4*)&Bs[k][tc * 4];
        #pragma unroll
        for (int i = 0; i < 8; i++)
            #pragma unroll
            for (int j = 0; j < 4; j++) acc[i][j] = fmaf(a[i], b[j], acc[i][j]);
    }
    #pragma unroll
    for (int i = 0; i < 8; i++) {
        int gr = rowBase + tr * 8 + i;
        if (gr >= N_NODES) continue;
        *(float4*)&out[(size_t)gr * IN_CH + colBase + tc * 4] = *(float4*)&acc[i][0];
    }
}

extern "C" void kernel_launch(void* const* d_in, const int* in_sizes, int n_in,
                              void* d_out, int out_size) {
    const float* x   = (const float*)d_in[0];
    const int*   ei  = (const int*)d_in[1];
    const float* W1  = (const float*)d_in[2];
    const float* aS1 = (const float*)d_in[3];
    const float* aD1 = (const float*)d_in[4];
    const float* b1  = (const float*)d_in[5];
    const float* W2  = (const float*)d_in[6];
    const float* aS2 = (const float*)d_in[7];
    const float* aD2 = (const float*)d_in[8];
    const float* b2  = (const float*)d_in[9];
    const float* Wd  = (const float*)d_in[10];
    const float* bd  = (const float*)d_in[11];
    (void)in_sizes; (void)n_in; (void)out_size;

    float* out  = (float*)d_out;
    float* outZ = out + (size_t)N_NODES * IN_CH;

    static cudaStream_t s2 = nullptr;
    static cudaEvent_t evFork = nullptr, evJoin = nullptr;
    if (s2 == nullptr) {
        cudaStreamCreateWithFlags(&s2, cudaStreamNonBlocking);
        cudaEventCreateWithFlags(&evFork, cudaEventDisableTiming);
        cudaEventCreateWithFlags(&evJoin, cudaEventDisableTiming);
    }

    cudaEventRecord(evFork, 0);
    cudaStreamWaitEvent(s2, evFork, 0);
    k_zero_rowptr<<<(N_NODES + 1 + 255) / 256, 256, 0, s2>>>();
    k_count<<<(ET + 255) / 256, 256, 0, s2>>>(ei);
    k_scan<<<1, 1024, 0, s2>>>();
    k_scatter<<<(ET + 255) / 256, 256, 0, s2>>>(ei);
    cudaEventRecord(evJoin, s2);

    {
        dim3 grid(F1 / BN1, M_PAD / BM);
        k_gemm_tf32<<<grid, 256>>>(x, W1, aS1, aD1);
    }

    cudaStreamWaitEvent(0, evJoin, 0);

    k_agg1<<<(2 * N_NODES * 32 + 255) / 256, 256>>>(b1);

    k_gemm2_tf32<<<M_PAD / BM, 256>>>(W2);
    k_logits2<<<(N_NODES * 32 + 255) / 256, 256>>>(aS2, aD2);
    k_agg2<<<(N_NODES * 32 + 255) / 256, 256>>>(b2, outZ);

    {
        dim3 grid(IN_CH / DBN, (N_NODES + BM - 1) / BM);
        k_decodert<<<grid, 256>>>(Wd, bd, out, outZ);
    }
}